// round 16
// baseline (speedup 1.0000x reference)
#include <cuda_runtime.h>
#include <cuda_bf16.h>
#include <math.h>

#define B_ 2
#define S_ 4096
#define E_ 1024
#define D_ 64
#define WIN_ 5
#define DIL_ 2

// Scratch (allocation-free rule: __device__ globals)
__device__ float g_Q[B_ * S_ * D_];
__device__ float g_K[B_ * S_ * D_];
__device__ float g_V[B_ * S_ * D_];
__device__ float g_Vsum[B_ * D_];
// W merged+split: [k2][col], col = mat*64 + n, u32 = packed bf16 {2k2, 2k2+1}
__device__ unsigned g_Wbhi[(E_ / 2) * 192];
__device__ unsigned g_Wblo[(E_ / 2) * 192];
// software barrier counter (monotonic across graph replays; epoch = cnt/128)
__device__ unsigned g_cnt;

// ---------------------------------------------------------------------------
// helpers
// ---------------------------------------------------------------------------
__device__ __forceinline__ unsigned pack_bf16(float lo_val, float hi_val) {
    __nv_bfloat162 p;
    p.x = __float2bfloat16(lo_val);
    p.y = __float2bfloat16(hi_val);
    return *(unsigned*)&p;
}
__device__ __forceinline__ float bf_residual(float v) {
    __nv_bfloat16 h = __float2bfloat16(v);
    return v - __bfloat162float(h);
}
__device__ __forceinline__ void mma_bf16(float* c, const unsigned* a, const unsigned* b) {
    asm volatile(
        "mma.sync.aligned.m16n8k16.row.col.f32.bf16.bf16.f32 "
        "{%0,%1,%2,%3}, {%4,%5,%6,%7}, {%8,%9}, {%0,%1,%2,%3};"
        : "+f"(c[0]), "+f"(c[1]), "+f"(c[2]), "+f"(c[3])
        : "r"(a[0]), "r"(a[1]), "r"(a[2]), "r"(a[3]), "r"(b[0]), "r"(b[1]));
}
__device__ __forceinline__ void cp_async16(unsigned smem_addr, const void* gptr) {
    asm volatile("cp.async.cg.shared.global [%0], [%1], 16;"
                 :: "r"(smem_addr), "l"(gptr) : "memory");
}
__device__ __forceinline__ void cp_commit() {
    asm volatile("cp.async.commit_group;" ::: "memory");
}
__device__ __forceinline__ void cp_wait0() {
    asm volatile("cp.async.wait_group 0;" ::: "memory");
}

// ---------------------------------------------------------------------------
// Kernel 1: MERGED QKV GEMM, 3xBF16 (hh+lh+hl) on m16n8k16, BK=32.
// Pre-phase (fused, replaces the wsplit kernel): the 128 co-resident blocks
// cooperatively convert W -> bf16 hi/lo planes (768 u32-pairs per block),
// block 0 seeds g_Vsum = S*bv, then a global software barrier (all blocks
// resident: grid 128 <= 148 SMs) orders conversion before consumption.
// Main phase: BM=64, 256 thr = 8 warps (2m x 4n), warp tile 32x48;
// B staged via cp.async.cg; A split at STS; V column sums fused in epilogue.
// ---------------------------------------------------------------------------
#define BM 64
#define SA 20     // As row stride (u32)
#define SB 200    // Bs row stride (u32); 800B rows, 16B-aligned

#define OFF_AH(s) ((s) * 8960)
#define OFF_AL(s) ((s) * 8960 + 1280)
#define OFF_BH(s) ((s) * 8960 + 2560)
#define OFF_BL(s) ((s) * 8960 + 5760)
#define SMEM_U32  17920

__global__ __launch_bounds__(256) void qkv_gemm_merged(
    const float* __restrict__ x,
    const float* __restrict__ Wq, const float* __restrict__ bq,
    const float* __restrict__ Wk, const float* __restrict__ bk,
    const float* __restrict__ Wv, const float* __restrict__ bv)
{
    extern __shared__ unsigned sm[];
    const unsigned smb = (unsigned)__cvta_generic_to_shared(sm);

    const int tid  = threadIdx.x;

    // ---------------- pre-phase: W split + Vsum seed + global barrier ------
    {
        const int base = blockIdx.x * 768;
#pragma unroll
        for (int i = 0; i < 3; i++) {
            const int idx = base + tid + 256 * i;      // < 98304
            const int k2 = idx / 192;
            const int c  = idx - k2 * 192;
            const int mat = c >> 6;
            const int n = c & 63;
            const float* src = (mat == 0) ? Wq : (mat == 1) ? Wk : Wv;
            const float v0 = src[(size_t)(2 * k2) * D_ + n];
            const float v1 = src[(size_t)(2 * k2 + 1) * D_ + n];
            g_Wbhi[idx] = pack_bf16(v0, v1);
            g_Wblo[idx] = pack_bf16(bf_residual(v0), bf_residual(v1));
        }
        if (blockIdx.x == 0 && tid < B_ * D_) {
            g_Vsum[tid] = (float)S_ * bv[tid & (D_ - 1)];
        }
        __threadfence();
        __syncthreads();                    // all block writes fenced
        if (tid == 0) {
            const unsigned arrival = atomicAdd(&g_cnt, 1u);
            const unsigned target = (arrival / 128u + 1u) * 128u;
            while (atomicAdd(&g_cnt, 0u) < target) { __nanosleep(64); }
            __threadfence();                // acquire side
        }
        __syncthreads();
    }

    // ---------------- main GEMM phase --------------------------------------
    const int lane = tid & 31;
    const int wid  = tid >> 5;
    const int wm   = wid >> 2;      // 0..1 -> m0 = wm*32
    const int wn   = wid & 3;       // 0..3 -> n0 = wn*48
    const int rowBase = blockIdx.x * BM;
    const int bb = rowBase >> 12;

    const int arow = tid >> 2;          // 0..63
    const int af   = tid & 3;           // 0..3
    const float* aptr = x + (size_t)(rowBase + arow) * E_ + af * 8;

    float acc[2][6][4];
#pragma unroll
    for (int mt = 0; mt < 2; mt++)
#pragma unroll
        for (int nt = 0; nt < 6; nt++)
#pragma unroll
            for (int k = 0; k < 4; k++) acc[mt][nt][k] = 0.f;

    const int r  = lane >> 2;
    const int cc = lane & 3;
    const int m0 = wm * 32;
    const int n0 = wn * 48;

    float4 pa0, pa1;

    auto load_A = [&](int kt) {
        pa0 = *(const float4*)(aptr + kt * 32);
        pa1 = *(const float4*)(aptr + kt * 32 + 4);
    };

    // B: per stage 2 planes x 16 rows x 192 u32 = 1536 16B-chunks.
    auto issue_B = [&](int kt, int st) {
#pragma unroll
        for (int i = 0; i < 6; i++) {
            const int e = tid + 256 * i;
            const bool lo = (i >= 3);
            const int f = e - (lo ? 768 : 0);
            const int row = f / 48;
            const int c = (f - row * 48) * 4;
            const unsigned* gsrc = (lo ? g_Wblo : g_Wbhi)
                + (size_t)(kt * 16 + row) * 192 + c;
            const unsigned dst = smb +
                ((lo ? OFF_BL(st) : OFF_BH(st)) + row * SB + c) * 4u;
            cp_async16(dst, gsrc);
        }
        cp_commit();
    };

    auto store_A = [&](int st) {
        uint4 h, l;
        h.x = pack_bf16(pa0.x, pa0.y);
        h.y = pack_bf16(pa0.z, pa0.w);
        h.z = pack_bf16(pa1.x, pa1.y);
        h.w = pack_bf16(pa1.z, pa1.w);
        l.x = pack_bf16(bf_residual(pa0.x), bf_residual(pa0.y));
        l.y = pack_bf16(bf_residual(pa0.z), bf_residual(pa0.w));
        l.z = pack_bf16(bf_residual(pa1.x), bf_residual(pa1.y));
        l.w = pack_bf16(bf_residual(pa1.z), bf_residual(pa1.w));
        *(uint4*)&sm[OFF_AH(st) + arow * SA + af * 4] = h;
        *(uint4*)&sm[OFF_AL(st) + arow * SA + af * 4] = l;
    };

    auto compute_tile = [&](int st) {
        const unsigned* AH = sm + OFF_AH(st);
        const unsigned* AL = sm + OFF_AL(st);
        const unsigned* BH = sm + OFF_BH(st);
        const unsigned* BL = sm + OFF_BL(st);
#pragma unroll
        for (int ks = 0; ks < 2; ks++) {
            const int kc = ks * 8 + cc;
            unsigned ah[2][4], al[2][4];
#pragma unroll
            for (int mt = 0; mt < 2; mt++) {
                const int mr = m0 + mt * 16 + r;
                ah[mt][0] = AH[mr * SA + kc];
                ah[mt][1] = AH[(mr + 8) * SA + kc];
                ah[mt][2] = AH[mr * SA + kc + 4];
                ah[mt][3] = AH[(mr + 8) * SA + kc + 4];
                al[mt][0] = AL[mr * SA + kc];
                al[mt][1] = AL[(mr + 8) * SA + kc];
                al[mt][2] = AL[mr * SA + kc + 4];
                al[mt][3] = AL[(mr + 8) * SA + kc + 4];
            }
            unsigned bh[6][2], bl[6][2];
#pragma unroll
            for (int nt = 0; nt < 6; nt++) {
                const int n = n0 + nt * 8 + r;
                bh[nt][0] = BH[kc * SB + n];
                bh[nt][1] = BH[(kc + 4) * SB + n];
                bl[nt][0] = BL[kc * SB + n];
                bl[nt][1] = BL[(kc + 4) * SB + n];
            }
#pragma unroll
            for (int mt = 0; mt < 2; mt++)
#pragma unroll
                for (int nt = 0; nt < 6; nt++) mma_bf16(acc[mt][nt], ah[mt], bh[nt]);
#pragma unroll
            for (int mt = 0; mt < 2; mt++)
#pragma unroll
                for (int nt = 0; nt < 6; nt++) mma_bf16(acc[mt][nt], al[mt], bh[nt]);
#pragma unroll
            for (int mt = 0; mt < 2; mt++)
#pragma unroll
                for (int nt = 0; nt < 6; nt++) mma_bf16(acc[mt][nt], ah[mt], bl[nt]);
        }
    };

    // prologue: tile 0 -> stage 0
    load_A(0);
    issue_B(0, 0);
    store_A(0);
    cp_wait0();
    __syncthreads();

    const int KTILES = E_ / 32;   // 32
    for (int kt = 1; kt < KTILES; kt++) {
        load_A(kt);
        issue_B(kt, kt & 1);
        compute_tile((kt - 1) & 1);
        store_A(kt & 1);
        cp_wait0();
        __syncthreads();
    }
    compute_tile((KTILES - 1) & 1);

    // epilogue: route 8-col groups to Q/K/V with bias; fuse V column sums
#pragma unroll
    for (int nt = 0; nt < 6; nt++) {
        const int colbase = n0 + nt * 8;
        const int mat = colbase >> 6;
        const int ocolb = colbase & 63;
        float* op = (mat == 0) ? g_Q : (mat == 1) ? g_K : g_V;
        const float* bp = (mat == 0) ? bq : (mat == 1) ? bk : bv;
        const int ocol = ocolb + 2 * cc;
        const float b0v = bp[ocol];
        const float b1v = bp[ocol + 1];
#pragma unroll
        for (int mt = 0; mt < 2; mt++) {
            const int row0 = rowBase + m0 + mt * 16 + r;
            float2 v0 = make_float2(acc[mt][nt][0] + b0v, acc[mt][nt][1] + b1v);
            float2 v1 = make_float2(acc[mt][nt][2] + b0v, acc[mt][nt][3] + b1v);
            *(float2*)&op[(size_t)row0 * D_ + ocol] = v0;
            *(float2*)&op[(size_t)(row0 + 8) * D_ + ocol] = v1;
        }
        if (mat == 2) {
            float s0 = acc[0][nt][0] + acc[0][nt][2] + acc[1][nt][0] + acc[1][nt][2];
            float s1 = acc[0][nt][1] + acc[0][nt][3] + acc[1][nt][1] + acc[1][nt][3];
#pragma unroll
            for (int o = 4; o < 32; o <<= 1) {
                s0 += __shfl_xor_sync(0xffffffffu, s0, o);
                s1 += __shfl_xor_sync(0xffffffffu, s1, o);
            }
            if (r == 0) {
                atomicAdd(&g_Vsum[bb * D_ + ocol], s0);
                atomicAdd(&g_Vsum[bb * D_ + ocol + 1], s1);
            }
        }
    }
}

// ---------------------------------------------------------------------------
// Kernel 2: windowed attention combine, branch-free. One warp per (b, i).
// out[i] = [ e0*Vsum + sum_w (e_w - e0)*V[j_w] ] / [ sum_w e_w + e0*(S - nv) ]
// ---------------------------------------------------------------------------
__global__ __launch_bounds__(256) void attn_kernel(float* __restrict__ out)
{
    const int gw = (blockIdx.x * blockDim.x + threadIdx.x) >> 5;
    const int lane = threadIdx.x & 31;
    if (gw >= B_ * S_) return;

    const int b = gw >> 12;
    const int i = gw & (S_ - 1);

    const float* Qr = g_Q + (size_t)gw * D_;
    const float q0 = Qr[lane];
    const float q1 = Qr[lane + 32];
    const float* Kb = g_K + (size_t)b * S_ * D_;
    const float* Vb = g_V + (size_t)b * S_ * D_;

    float p[WIN_], vm[WIN_], v0[WIN_], v1[WIN_];
    int nv = 0;

#pragma unroll
    for (int w = 0; w < WIN_; w++) {
        const int j = i + DIL_ * (w - WIN_ / 2);
        const bool valid = (j >= 0) && (j < S_);
        vm[w] = valid ? 1.f : 0.f;
        nv += valid;
        const int jc = j < 0 ? 0 : (j >= S_ ? S_ - 1 : j);
        const float* Kr = Kb + (size_t)jc * D_;
        p[w] = q0 * Kr[lane] + q1 * Kr[lane + 32];
        const float* Vr = Vb + (size_t)jc * D_;
        v0[w] = Vr[lane];
        v1[w] = Vr[lane + 32];
    }

#pragma unroll
    for (int o = 16; o > 0; o >>= 1) {
#pragma unroll
        for (int w = 0; w < WIN_; w++)
            p[w] += __shfl_xor_sync(0xffffffffu, p[w], o);
    }

    float cmax = 0.f;
#pragma unroll
    for (int w = 0; w < WIN_; w++) cmax = fmaxf(cmax, vm[w] * p[w]);

    const float e0 = expf(-cmax);
    float denom = e0 * (float)(S_ - nv);
    float a0 = e0 * g_Vsum[b * D_ + lane];
    float a1 = e0 * g_Vsum[b * D_ + lane + 32];

#pragma unroll
    for (int w = 0; w < WIN_; w++) {
        const float ew = expf(p[w] - cmax) * vm[w];
        denom += ew;
        const float f = ew - e0 * vm[w];
        a0 = fmaf(f, v0[w], a0);
        a1 = fmaf(f, v1[w], a1);
    }

    const float inv = 1.f / denom;
    out[(size_t)gw * D_ + lane] = a0 * inv;
    out[(size_t)gw * D_ + lane + 32] = a1 * inv;
}

// ---------------------------------------------------------------------------
extern "C" void kernel_launch(void* const* d_in, const int* in_sizes, int n_in,
                              void* d_out, int out_size)
{
    const float* x  = (const float*)d_in[0];
    const float* Wq = (const float*)d_in[1];
    const float* bq = (const float*)d_in[2];
    const float* Wk = (const float*)d_in[3];
    const float* bk = (const float*)d_in[4];
    const float* Wv = (const float*)d_in[5];
    const float* bv = (const float*)d_in[6];
    float* out = (float*)d_out;

    static int configured = 0;
    if (!configured) {
        cudaFuncSetAttribute(qkv_gemm_merged,
                             cudaFuncAttributeMaxDynamicSharedMemorySize,
                             SMEM_U32 * 4);
        configured = 1;
    }

    qkv_gemm_merged<<<(B_ * S_) / BM, 256, SMEM_U32 * 4>>>(
        x, Wq, bq, Wk, bk, Wv, bv);

    const int warps = B_ * S_;
    attn_kernel<<<(warps * 32 + 255) / 256, 256>>>(out);
}

// round 17
// speedup vs baseline: 1.0447x; 1.0447x over previous
#include <cuda_runtime.h>
#include <cuda_bf16.h>
#include <math.h>

#define B_ 2
#define S_ 4096
#define E_ 1024
#define D_ 64
#define WIN_ 5
#define DIL_ 2

// Scratch (allocation-free rule: __device__ globals)
__device__ float g_Q[B_ * S_ * D_];
__device__ float g_K[B_ * S_ * D_];
__device__ float g_V[B_ * S_ * D_];
__device__ float g_Vsum[B_ * D_];
// W merged+split: [k2][col], col = mat*64 + n, u32 = packed bf16 {2k2, 2k2+1}
__device__ unsigned g_Wbhi[(E_ / 2) * 192];
__device__ unsigned g_Wblo[(E_ / 2) * 192];

// ---------------------------------------------------------------------------
// helpers
// ---------------------------------------------------------------------------
__device__ __forceinline__ unsigned pack_bf16(float lo_val, float hi_val) {
    __nv_bfloat162 p;
    p.x = __float2bfloat16(lo_val);
    p.y = __float2bfloat16(hi_val);
    return *(unsigned*)&p;
}
__device__ __forceinline__ float bf_residual(float v) {
    __nv_bfloat16 h = __float2bfloat16(v);
    return v - __bfloat162float(h);
}
__device__ __forceinline__ void mma_bf16(float* c, const unsigned* a, const unsigned* b) {
    asm volatile(
        "mma.sync.aligned.m16n8k16.row.col.f32.bf16.bf16.f32 "
        "{%0,%1,%2,%3}, {%4,%5,%6,%7}, {%8,%9}, {%0,%1,%2,%3};"
        : "+f"(c[0]), "+f"(c[1]), "+f"(c[2]), "+f"(c[3])
        : "r"(a[0]), "r"(a[1]), "r"(a[2]), "r"(a[3]), "r"(b[0]), "r"(b[1]));
}
__device__ __forceinline__ void cp_async16(unsigned smem_addr, const void* gptr) {
    asm volatile("cp.async.cg.shared.global [%0], [%1], 16;"
                 :: "r"(smem_addr), "l"(gptr) : "memory");
}
__device__ __forceinline__ void cp_commit() {
    asm volatile("cp.async.commit_group;" ::: "memory");
}
__device__ __forceinline__ void cp_wait0() {
    asm volatile("cp.async.wait_group 0;" ::: "memory");
}

// ---------------------------------------------------------------------------
// Kernel 0: W -> merged packed bf16 hi/lo planes, [k2][col]. One u32-pair
// per thread. Also seeds g_Vsum = S*bv. (R14 version — standalone.)
// ---------------------------------------------------------------------------
__global__ void wsplit_kernel(const float* __restrict__ Wq,
                              const float* __restrict__ Wk,
                              const float* __restrict__ Wv,
                              const float* __restrict__ bv)
{
    const int idx = blockIdx.x * blockDim.x + threadIdx.x;
    if (blockIdx.x == 0 && threadIdx.x < B_ * D_) {
        g_Vsum[threadIdx.x] = (float)S_ * bv[threadIdx.x & (D_ - 1)];
    }
    if (idx >= (E_ / 2) * 192) return;
    const int k2 = idx / 192;
    const int c  = idx - k2 * 192;
    const int mat = c >> 6;
    const int n = c & 63;
    const float* src = (mat == 0) ? Wq : (mat == 1) ? Wk : Wv;
    const float v0 = src[(size_t)(2 * k2) * D_ + n];
    const float v1 = src[(size_t)(2 * k2 + 1) * D_ + n];
    g_Wbhi[idx] = pack_bf16(v0, v1);
    g_Wblo[idx] = pack_bf16(bf_residual(v0), bf_residual(v1));
}

// ---------------------------------------------------------------------------
// Kernel 1: MERGED QKV GEMM, 3xBF16 (hh+lh+hl) on m16n8k16, BK=32.
// (R14 configuration — unchanged; at the bf16 mma.sync pipe floor.)
// ---------------------------------------------------------------------------
#define BM 64
#define SA 20     // As row stride (u32)
#define SB 200    // Bs row stride (u32); 800B rows, 16B-aligned

#define OFF_AH(s) ((s) * 8960)
#define OFF_AL(s) ((s) * 8960 + 1280)
#define OFF_BH(s) ((s) * 8960 + 2560)
#define OFF_BL(s) ((s) * 8960 + 5760)
#define SMEM_U32  17920

__global__ __launch_bounds__(256) void qkv_gemm_merged(
    const float* __restrict__ x,
    const float* __restrict__ bq,
    const float* __restrict__ bk,
    const float* __restrict__ bv)
{
    extern __shared__ unsigned sm[];
    const unsigned smb = (unsigned)__cvta_generic_to_shared(sm);

    const int tid  = threadIdx.x;
    const int lane = tid & 31;
    const int wid  = tid >> 5;
    const int wm   = wid >> 2;      // 0..1 -> m0 = wm*32
    const int wn   = wid & 3;       // 0..3 -> n0 = wn*48
    const int rowBase = blockIdx.x * BM;
    const int bb = rowBase >> 12;

    const int arow = tid >> 2;          // 0..63
    const int af   = tid & 3;           // 0..3
    const float* aptr = x + (size_t)(rowBase + arow) * E_ + af * 8;

    float acc[2][6][4];
#pragma unroll
    for (int mt = 0; mt < 2; mt++)
#pragma unroll
        for (int nt = 0; nt < 6; nt++)
#pragma unroll
            for (int k = 0; k < 4; k++) acc[mt][nt][k] = 0.f;

    const int r  = lane >> 2;
    const int cc = lane & 3;
    const int m0 = wm * 32;
    const int n0 = wn * 48;

    float4 pa0, pa1;

    auto load_A = [&](int kt) {
        pa0 = *(const float4*)(aptr + kt * 32);
        pa1 = *(const float4*)(aptr + kt * 32 + 4);
    };

    // B: per stage 2 planes x 16 rows x 192 u32 = 1536 16B-chunks.
    auto issue_B = [&](int kt, int st) {
#pragma unroll
        for (int i = 0; i < 6; i++) {
            const int e = tid + 256 * i;
            const bool lo = (i >= 3);
            const int f = e - (lo ? 768 : 0);
            const int row = f / 48;
            const int c = (f - row * 48) * 4;
            const unsigned* gsrc = (lo ? g_Wblo : g_Wbhi)
                + (size_t)(kt * 16 + row) * 192 + c;
            const unsigned dst = smb +
                ((lo ? OFF_BL(st) : OFF_BH(st)) + row * SB + c) * 4u;
            cp_async16(dst, gsrc);
        }
        cp_commit();
    };

    auto store_A = [&](int st) {
        uint4 h, l;
        h.x = pack_bf16(pa0.x, pa0.y);
        h.y = pack_bf16(pa0.z, pa0.w);
        h.z = pack_bf16(pa1.x, pa1.y);
        h.w = pack_bf16(pa1.z, pa1.w);
        l.x = pack_bf16(bf_residual(pa0.x), bf_residual(pa0.y));
        l.y = pack_bf16(bf_residual(pa0.z), bf_residual(pa0.w));
        l.z = pack_bf16(bf_residual(pa1.x), bf_residual(pa1.y));
        l.w = pack_bf16(bf_residual(pa1.z), bf_residual(pa1.w));
        *(uint4*)&sm[OFF_AH(st) + arow * SA + af * 4] = h;
        *(uint4*)&sm[OFF_AL(st) + arow * SA + af * 4] = l;
    };

    auto compute_tile = [&](int st) {
        const unsigned* AH = sm + OFF_AH(st);
        const unsigned* AL = sm + OFF_AL(st);
        const unsigned* BH = sm + OFF_BH(st);
        const unsigned* BL = sm + OFF_BL(st);
#pragma unroll
        for (int ks = 0; ks < 2; ks++) {
            const int kc = ks * 8 + cc;
            unsigned ah[2][4], al[2][4];
#pragma unroll
            for (int mt = 0; mt < 2; mt++) {
                const int mr = m0 + mt * 16 + r;
                ah[mt][0] = AH[mr * SA + kc];
                ah[mt][1] = AH[(mr + 8) * SA + kc];
                ah[mt][2] = AH[mr * SA + kc + 4];
                ah[mt][3] = AH[(mr + 8) * SA + kc + 4];
                al[mt][0] = AL[mr * SA + kc];
                al[mt][1] = AL[(mr + 8) * SA + kc];
                al[mt][2] = AL[mr * SA + kc + 4];
                al[mt][3] = AL[(mr + 8) * SA + kc + 4];
            }
            unsigned bh[6][2], bl[6][2];
#pragma unroll
            for (int nt = 0; nt < 6; nt++) {
                const int n = n0 + nt * 8 + r;
                bh[nt][0] = BH[kc * SB + n];
                bh[nt][1] = BH[(kc + 4) * SB + n];
                bl[nt][0] = BL[kc * SB + n];
                bl[nt][1] = BL[(kc + 4) * SB + n];
            }
#pragma unroll
            for (int mt = 0; mt < 2; mt++)
#pragma unroll
                for (int nt = 0; nt < 6; nt++) mma_bf16(acc[mt][nt], ah[mt], bh[nt]);
#pragma unroll
            for (int mt = 0; mt < 2; mt++)
#pragma unroll
                for (int nt = 0; nt < 6; nt++) mma_bf16(acc[mt][nt], al[mt], bh[nt]);
#pragma unroll
            for (int mt = 0; mt < 2; mt++)
#pragma unroll
                for (int nt = 0; nt < 6; nt++) mma_bf16(acc[mt][nt], ah[mt], bl[nt]);
        }
    };

    // prologue: tile 0 -> stage 0
    load_A(0);
    issue_B(0, 0);
    store_A(0);
    cp_wait0();
    __syncthreads();

    const int KTILES = E_ / 32;   // 32
    for (int kt = 1; kt < KTILES; kt++) {
        load_A(kt);
        issue_B(kt, kt & 1);
        compute_tile((kt - 1) & 1);
        store_A(kt & 1);
        cp_wait0();
        __syncthreads();
    }
    compute_tile((KTILES - 1) & 1);

    // epilogue: route 8-col groups to Q/K/V with bias; fuse V column sums
#pragma unroll
    for (int nt = 0; nt < 6; nt++) {
        const int colbase = n0 + nt * 8;
        const int mat = colbase >> 6;
        const int ocolb = colbase & 63;
        float* op = (mat == 0) ? g_Q : (mat == 1) ? g_K : g_V;
        const float* bp = (mat == 0) ? bq : (mat == 1) ? bk : bv;
        const int ocol = ocolb + 2 * cc;
        const float b0v = bp[ocol];
        const float b1v = bp[ocol + 1];
#pragma unroll
        for (int mt = 0; mt < 2; mt++) {
            const int row0 = rowBase + m0 + mt * 16 + r;
            float2 v0 = make_float2(acc[mt][nt][0] + b0v, acc[mt][nt][1] + b1v);
            float2 v1 = make_float2(acc[mt][nt][2] + b0v, acc[mt][nt][3] + b1v);
            *(float2*)&op[(size_t)row0 * D_ + ocol] = v0;
            *(float2*)&op[(size_t)(row0 + 8) * D_ + ocol] = v1;
        }
        if (mat == 2) {
            float s0 = acc[0][nt][0] + acc[0][nt][2] + acc[1][nt][0] + acc[1][nt][2];
            float s1 = acc[0][nt][1] + acc[0][nt][3] + acc[1][nt][1] + acc[1][nt][3];
#pragma unroll
            for (int o = 4; o < 32; o <<= 1) {
                s0 += __shfl_xor_sync(0xffffffffu, s0, o);
                s1 += __shfl_xor_sync(0xffffffffu, s1, o);
            }
            if (r == 0) {
                atomicAdd(&g_Vsum[bb * D_ + ocol], s0);
                atomicAdd(&g_Vsum[bb * D_ + ocol + 1], s1);
            }
        }
    }
}

// ---------------------------------------------------------------------------
// Kernel 2: windowed attention combine, branch-free, float2-vectorized.
// One warp per (b, i); lane covers dims {2*lane, 2*lane+1} -> 13 wide
// memory ops instead of 24 scalar ones.
// out[i] = [ e0*Vsum + sum_w (e_w - e0)*V[j_w] ] / [ sum_w e_w + e0*(S - nv) ]
// ---------------------------------------------------------------------------
__global__ __launch_bounds__(256) void attn_kernel(float* __restrict__ out)
{
    const int gw = (blockIdx.x * blockDim.x + threadIdx.x) >> 5;
    const int lane = threadIdx.x & 31;
    if (gw >= B_ * S_) return;

    const int b = gw >> 12;
    const int i = gw & (S_ - 1);
    const int d2 = lane * 2;

    const float2 q = *(const float2*)(g_Q + (size_t)gw * D_ + d2);
    const float* Kb = g_K + (size_t)b * S_ * D_;
    const float* Vb = g_V + (size_t)b * S_ * D_;

    float p[WIN_], vm[WIN_];
    float2 v[WIN_];
    int nv = 0;

    // issue all K partial-products and V prefetches
#pragma unroll
    for (int w = 0; w < WIN_; w++) {
        const int j = i + DIL_ * (w - WIN_ / 2);
        const bool valid = (j >= 0) && (j < S_);
        vm[w] = valid ? 1.f : 0.f;
        nv += valid;
        const int jc = j < 0 ? 0 : (j >= S_ ? S_ - 1 : j);
        const float2 kv = *(const float2*)(Kb + (size_t)jc * D_ + d2);
        p[w] = q.x * kv.x + q.y * kv.y;
        v[w] = *(const float2*)(Vb + (size_t)jc * D_ + d2);
    }

    // 5 interleaved shfl reduction chains (each lane holds 2-dim partial)
#pragma unroll
    for (int o = 16; o > 0; o >>= 1) {
#pragma unroll
        for (int w = 0; w < WIN_; w++)
            p[w] += __shfl_xor_sync(0xffffffffu, p[w], o);
    }

    float cmax = 0.f;
#pragma unroll
    for (int w = 0; w < WIN_; w++) cmax = fmaxf(cmax, vm[w] * p[w]);

    const float2 vs = *(const float2*)(g_Vsum + b * D_ + d2);
    const float e0 = expf(-cmax);
    float denom = e0 * (float)(S_ - nv);
    float a0 = e0 * vs.x;
    float a1 = e0 * vs.y;

#pragma unroll
    for (int w = 0; w < WIN_; w++) {
        const float ew = expf(p[w] - cmax) * vm[w];
        denom += ew;
        const float f = ew - e0 * vm[w];
        a0 = fmaf(f, v[w].x, a0);
        a1 = fmaf(f, v[w].y, a1);
    }

    const float inv = 1.f / denom;
    float2 o2 = make_float2(a0 * inv, a1 * inv);
    *(float2*)(out + (size_t)gw * D_ + d2) = o2;
}

// ---------------------------------------------------------------------------
extern "C" void kernel_launch(void* const* d_in, const int* in_sizes, int n_in,
                              void* d_out, int out_size)
{
    const float* x  = (const float*)d_in[0];
    const float* Wq = (const float*)d_in[1];
    const float* bq = (const float*)d_in[2];
    const float* Wk = (const float*)d_in[3];
    const float* bk = (const float*)d_in[4];
    const float* Wv = (const float*)d_in[5];
    const float* bv = (const float*)d_in[6];
    float* out = (float*)d_out;

    static int configured = 0;
    if (!configured) {
        cudaFuncSetAttribute(qkv_gemm_merged,
                             cudaFuncAttributeMaxDynamicSharedMemorySize,
                             SMEM_U32 * 4);
        configured = 1;
    }

    wsplit_kernel<<<((E_ / 2) * 192 + 255) / 256, 256>>>(Wq, Wk, Wv, bv);

    qkv_gemm_merged<<<(B_ * S_) / BM, 256, SMEM_U32 * 4>>>(x, bq, bk, bv);

    const int warps = B_ * S_;
    attn_kernel<<<(warps * 32 + 255) / 256, 256>>>(out);
}